// round 1
// baseline (speedup 1.0000x reference)
#include <cuda_runtime.h>
#include <math.h>

// ---------------------------------------------------------------------------
// HGATv2 layer: 3 GATv2 edge types + hetero-max + BN + ELU
// Sizes fixed by the problem: n_op=50000, n_m=10000, E=400000, DIN=128, H=4, C=64
// ---------------------------------------------------------------------------

#define HC 256          // H*C
#define CC 64           // C
#define DIN 128
#define NEG_SLOPE 0.2f

#define MAX_NOP 50000
#define MAX_NM  10000
#define MAX_E   400000
#define MAX_EOO (MAX_E + MAX_NOP)

// ---- float scratch layout (element offsets) ----
#define OFF_XL_OO   0ll
#define OFF_XR_OO   12800000ll
#define OFF_XL_OM   25600000ll
#define OFF_XR_MO   38400000ll
#define OFF_XR_OM   51200000ll
#define OFF_XL_MO   53760000ll
#define OFF_RES_OO  56320000ll
#define OFF_RES_MO  59520000ll
#define OFF_RES_OM  62720000ll
#define OFF_S_OO    63360000ll
#define OFF_S_OM    65160000ll
#define OFF_S_MO    66760000ll
#define OFF_OUT_OO  68360000ll
#define OFF_OUT_MO  71560000ll
#define OFF_OUT_OM  74760000ll
#define OFF_TMP_OP  75400000ll
#define OFF_TMP_M   78600000ll
#define OFF_BN      79240000ll   // [sum_op 64 | sq_op 64 | sum_m 64 | sq_m 64]
#define TOTAL_F     79240256ll

// ---- int scratch layout ----
#define IOFF_CNT_OO   0ll
#define IOFF_OFS_OO   50000ll
#define IOFF_CUR_OO   100001ll
#define IOFF_EL_OO    150001ll
#define IOFF_CNT_OM   600001ll
#define IOFF_OFS_OM   610001ll
#define IOFF_CUR_OM   620002ll
#define IOFF_EL_OM    630002ll
#define IOFF_CNT_MO   1030002ll
#define IOFF_OFS_MO   1080002ll
#define IOFF_CUR_MO   1130003ll
#define IOFF_EL_MO    1180003ll
#define TOTAL_I       1580003ll

__device__ float g_fscratch[TOTAL_F];
__device__ int   g_iscratch[TOTAL_I];

// ---------------------------------------------------------------------------
// Tiled fp32 GEMM: C[M,N] = A[M,K] @ B[K,N], K multiple of 16, N multiple of 64
// ---------------------------------------------------------------------------
__global__ void sgemm(const float* __restrict__ A, const float* __restrict__ B,
                      float* __restrict__ C, int M, int N, int K)
{
    __shared__ float As[16][64];
    __shared__ float Bs[16][64];
    const int tid  = threadIdx.x;           // 256 threads
    const int brow = blockIdx.y * 64;
    const int bcol = blockIdx.x * 64;
    const int tr   = (tid >> 4) << 2;       // 0..60
    const int tc   = (tid & 15) << 2;       // 0..60

    float acc[4][4];
    #pragma unroll
    for (int i = 0; i < 4; i++)
        #pragma unroll
        for (int j = 0; j < 4; j++) acc[i][j] = 0.f;

    const int am = brow + (tid >> 2);       // row this thread loads for A
    const int ak = (tid & 3) << 2;          // k-offset within tile
    const int bk = tid >> 4;                // k row for B load
    const int bn = bcol + ((tid & 15) << 2);

    for (int k0 = 0; k0 < K; k0 += 16) {
        float4 av = make_float4(0.f, 0.f, 0.f, 0.f);
        if (am < M) av = *(const float4*)&A[(long long)am * K + k0 + ak];
        As[ak + 0][tid >> 2] = av.x;
        As[ak + 1][tid >> 2] = av.y;
        As[ak + 2][tid >> 2] = av.z;
        As[ak + 3][tid >> 2] = av.w;
        float4 bv = *(const float4*)&B[(long long)(k0 + bk) * N + bn];
        *(float4*)&Bs[bk][(tid & 15) << 2] = bv;
        __syncthreads();
        #pragma unroll
        for (int kk = 0; kk < 16; kk++) {
            float a[4], b[4];
            #pragma unroll
            for (int i = 0; i < 4; i++) a[i] = As[kk][tr + i];
            #pragma unroll
            for (int j = 0; j < 4; j++) b[j] = Bs[kk][tc + j];
            #pragma unroll
            for (int i = 0; i < 4; i++)
                #pragma unroll
                for (int j = 0; j < 4; j++) acc[i][j] += a[i] * b[j];
        }
        __syncthreads();
    }
    #pragma unroll
    for (int i = 0; i < 4; i++) {
        int row = brow + tr + i;
        if (row < M)
            *(float4*)&C[(long long)row * N + bcol + tc] =
                make_float4(acc[i][0], acc[i][1], acc[i][2], acc[i][3]);
    }
}

// ---------------------------------------------------------------------------
// CSR building: histogram -> single-block exclusive scan -> scatter
// ---------------------------------------------------------------------------
__global__ void hist_kernel(const int* __restrict__ dst, int ne, int E, int selfloop,
                            int* __restrict__ counts)
{
    int i = blockIdx.x * blockDim.x + threadIdx.x;
    if (i >= ne) return;
    int d = (selfloop && i >= E) ? (i - E) : dst[i];
    atomicAdd(&counts[d], 1);
}

__global__ void exscan_kernel(const int* __restrict__ counts, int* __restrict__ offsets, int n)
{
    __shared__ int sums[1024];
    int t = threadIdx.x;
    int chunk = (n + 1023) / 1024;
    int beg = t * chunk;
    int end = min(beg + chunk, n);
    int s = 0;
    for (int i = beg; i < end; i++) s += counts[i];
    sums[t] = s;
    __syncthreads();
    for (int o = 1; o < 1024; o <<= 1) {
        int v = (t >= o) ? sums[t - o] : 0;
        __syncthreads();
        sums[t] += v;
        __syncthreads();
    }
    int run = sums[t] - s;   // exclusive prefix for this chunk
    for (int i = beg; i < end; i++) { offsets[i] = run; run += counts[i]; }
    if (t == 1023) offsets[n] = sums[1023];
}

__global__ void scatter_kernel(const int* __restrict__ dst, int ne, int E, int selfloop,
                               const int* __restrict__ offsets, int* __restrict__ cursor,
                               int* __restrict__ elist)
{
    int i = blockIdx.x * blockDim.x + threadIdx.x;
    if (i >= ne) return;
    int d = (selfloop && i >= E) ? (i - E) : dst[i];
    int pos = offsets[d] + atomicAdd(&cursor[d], 1);
    elist[pos] = i;
}

// ---------------------------------------------------------------------------
// Edge logits: one warp per edge; s[e][h] = sum_c lrelu(xl+xr)*att[h][c]
// ---------------------------------------------------------------------------
__global__ void edge_logits(const float* __restrict__ XL, const float* __restrict__ XR,
                            const int* __restrict__ src, const int* __restrict__ dst,
                            int ne, int E, int selfloop,
                            const float* __restrict__ att, float* __restrict__ S)
{
    int gw   = (blockIdx.x * blockDim.x + threadIdx.x) >> 5;
    int lane = threadIdx.x & 31;
    if (gw >= ne) return;
    int si, di;
    if (selfloop && gw >= E) { si = di = gw - E; }
    else { si = src[gw]; di = dst[gw]; }

    const float4* xl = (const float4*)(XL + (long long)si * HC);
    const float4* xr = (const float4*)(XR + (long long)di * HC);
    const float4* at = (const float4*)att;
    int b = lane * 2;
    float acc = 0.f;
    #pragma unroll
    for (int q = 0; q < 2; q++) {
        float4 a = xl[b + q], r = xr[b + q], w = at[b + q];
        float vx = a.x + r.x; vx = vx > 0.f ? vx : NEG_SLOPE * vx;
        float vy = a.y + r.y; vy = vy > 0.f ? vy : NEG_SLOPE * vy;
        float vz = a.z + r.z; vz = vz > 0.f ? vz : NEG_SLOPE * vz;
        float vw = a.w + r.w; vw = vw > 0.f ? vw : NEG_SLOPE * vw;
        acc += vx * w.x + vy * w.y + vz * w.z + vw * w.w;
    }
    acc += __shfl_xor_sync(0xffffffffu, acc, 4);
    acc += __shfl_xor_sync(0xffffffffu, acc, 2);
    acc += __shfl_xor_sync(0xffffffffu, acc, 1);
    if ((lane & 7) == 0) S[(long long)gw * 4 + (lane >> 3)] = acc;
}

// ---------------------------------------------------------------------------
// Aggregation: one warp per destination node. Segment softmax + weighted sum,
// accumulators in registers (8 per lane = 256 per warp), then head-mean.
// ---------------------------------------------------------------------------
__global__ void aggregate(const float* __restrict__ XL, const float* __restrict__ S,
                          const int* __restrict__ offsets, const int* __restrict__ elist,
                          const int* __restrict__ src, int E, int selfloop,
                          int n_dst, float* __restrict__ OUT)
{
    int w    = (blockIdx.x * blockDim.x + threadIdx.x) >> 5;
    int lane = threadIdx.x & 31;
    if (w >= n_dst) return;
    int beg = offsets[w], end = offsets[w + 1];

    float m0 = -1e30f, m1 = -1e30f, m2 = -1e30f, m3 = -1e30f;
    for (int i = beg + lane; i < end; i += 32) {
        float4 sv = ((const float4*)S)[elist[i]];
        m0 = fmaxf(m0, sv.x); m1 = fmaxf(m1, sv.y);
        m2 = fmaxf(m2, sv.z); m3 = fmaxf(m3, sv.w);
    }
    #pragma unroll
    for (int o = 16; o > 0; o >>= 1) {
        m0 = fmaxf(m0, __shfl_xor_sync(0xffffffffu, m0, o));
        m1 = fmaxf(m1, __shfl_xor_sync(0xffffffffu, m1, o));
        m2 = fmaxf(m2, __shfl_xor_sync(0xffffffffu, m2, o));
        m3 = fmaxf(m3, __shfl_xor_sync(0xffffffffu, m3, o));
    }

    float acc[8];
    #pragma unroll
    for (int k = 0; k < 8; k++) acc[k] = 0.f;
    float d0 = 0.f, d1 = 0.f, d2 = 0.f, d3 = 0.f;
    const int head = lane >> 3;
    const int fb   = lane * 2;   // float4 index within a 256-float row

    for (int i = beg; i < end; i++) {
        int e = elist[i];
        float4 sv = ((const float4*)S)[e];
        float p0 = __expf(sv.x - m0);
        float p1 = __expf(sv.y - m1);
        float p2 = __expf(sv.z - m2);
        float p3 = __expf(sv.w - m3);
        d0 += p0; d1 += p1; d2 += p2; d3 += p3;
        float p = (head == 0) ? p0 : (head == 1) ? p1 : (head == 2) ? p2 : p3;
        int si = (selfloop && e >= E) ? (e - E) : src[e];
        const float4* xl = (const float4*)(XL + (long long)si * HC);
        float4 a = xl[fb], b2 = xl[fb + 1];
        acc[0] += p * a.x;  acc[1] += p * a.y;  acc[2] += p * a.z;  acc[3] += p * a.w;
        acc[4] += p * b2.x; acc[5] += p * b2.y; acc[6] += p * b2.z; acc[7] += p * b2.w;
    }

    d0 = fmaxf(d0, 1e-16f); d1 = fmaxf(d1, 1e-16f);
    d2 = fmaxf(d2, 1e-16f); d3 = fmaxf(d3, 1e-16f);
    float invd = 1.f / ((head == 0) ? d0 : (head == 1) ? d1 : (head == 2) ? d2 : d3);

    #pragma unroll
    for (int k = 0; k < 8; k++) {
        float v = acc[k] * invd;
        v += __shfl_xor_sync(0xffffffffu, v, 8);
        v += __shfl_xor_sync(0xffffffffu, v, 16);
        acc[k] = v * 0.25f;  // mean over 4 heads
    }
    if (lane < 8) {
        float4* op = (float4*)(OUT + (long long)w * CC);
        op[lane * 2]     = make_float4(acc[0], acc[1], acc[2], acc[3]);
        op[lane * 2 + 1] = make_float4(acc[4], acc[5], acc[6], acc[7]);
    }
}

// ---------------------------------------------------------------------------
// Epilogue: combine edge types, batch-norm stats, apply BN + ELU
// ---------------------------------------------------------------------------
__global__ void combine_op(const float* __restrict__ A, const float* __restrict__ RA,
                           const float* __restrict__ ba,
                           const float* __restrict__ B, const float* __restrict__ RB,
                           const float* __restrict__ bb,
                           float* __restrict__ T, int total)
{
    int i = blockIdx.x * blockDim.x + threadIdx.x;
    if (i >= total) return;
    int c = i & 63;
    float va = A[i] + RA[i] + ba[c];
    float vb = B[i] + RB[i] + bb[c];
    T[i] = fmaxf(va, vb);
}

__global__ void combine_m(const float* __restrict__ A, const float* __restrict__ RA,
                          const float* __restrict__ ba, float* __restrict__ T, int total)
{
    int i = blockIdx.x * blockDim.x + threadIdx.x;
    if (i >= total) return;
    T[i] = A[i] + RA[i] + ba[i & 63];
}

__global__ void bn_reduce(const float* __restrict__ X, int n, float* __restrict__ acc)
{
    int c  = threadIdx.x & 63;
    int r0 = threadIdx.x >> 6;   // 0..3
    float s = 0.f, q = 0.f;
    for (int r = blockIdx.x * 4 + r0; r < n; r += gridDim.x * 4) {
        float v = X[(long long)r * 64 + c];
        s += v; q += v * v;
    }
    __shared__ float sh[2][256];
    sh[0][threadIdx.x] = s; sh[1][threadIdx.x] = q;
    __syncthreads();
    if (threadIdx.x < 64) {
        #pragma unroll
        for (int k = 1; k < 4; k++) {
            s += sh[0][threadIdx.x + 64 * k];
            q += sh[1][threadIdx.x + 64 * k];
        }
        atomicAdd(&acc[c], s);
        atomicAdd(&acc[64 + c], q);
    }
}

__global__ void bn_apply(const float* __restrict__ X, const float* __restrict__ acc,
                         const float* __restrict__ gamma, const float* __restrict__ beta,
                         int n, float* __restrict__ out)
{
    int i = blockIdx.x * blockDim.x + threadIdx.x;
    if (i >= n * 64) return;
    int c = i & 63;
    float inv_n = 1.f / (float)n;
    float mu = acc[c] * inv_n;
    float var = acc[64 + c] * inv_n - mu * mu;
    float rstd = rsqrtf(var + 1e-5f);
    float y = (X[i] - mu) * rstd * gamma[c] + beta[c];
    out[i] = y > 0.f ? y : expm1f(y);
}

// ---------------------------------------------------------------------------
// Host launch
// ---------------------------------------------------------------------------
extern "C" void kernel_launch(void* const* d_in, const int* in_sizes, int n_in,
                              void* d_out, int out_size)
{
    const float* x_op   = (const float*)d_in[0];
    const float* x_m    = (const float*)d_in[1];
    const int*   e_oo   = (const int*)  d_in[2];
    const int*   src_om = (const int*)  d_in[3];
    const int*   dst_om = (const int*)  d_in[4];
    const int*   src_mo = (const int*)  d_in[5];
    const int*   dst_mo = (const int*)  d_in[6];
    const float* Wl_oo  = (const float*)d_in[7];
    const float* Wr_oo  = (const float*)d_in[8];
    const float* att_oo = (const float*)d_in[9];
    const float* bias_oo= (const float*)d_in[10];
    const float* Wres_oo= (const float*)d_in[11];
    const float* Wl_om  = (const float*)d_in[12];
    const float* Wr_om  = (const float*)d_in[13];
    const float* att_om = (const float*)d_in[14];
    const float* bias_om= (const float*)d_in[15];
    const float* Wres_om= (const float*)d_in[16];
    const float* Wl_mo  = (const float*)d_in[17];
    const float* Wr_mo  = (const float*)d_in[18];
    const float* att_mo = (const float*)d_in[19];
    const float* bias_mo= (const float*)d_in[20];
    const float* Wres_mo= (const float*)d_in[21];
    const float* g_op   = (const float*)d_in[22];
    const float* b_op   = (const float*)d_in[23];
    const float* g_m    = (const float*)d_in[24];
    const float* b_m    = (const float*)d_in[25];

    const int n_op = in_sizes[0] / DIN;
    const int n_m  = in_sizes[1] / DIN;
    const int E    = in_sizes[3];
    const int Eoo  = E + n_op;

    float* sc; cudaGetSymbolAddress((void**)&sc, g_fscratch);
    int*   is; cudaGetSymbolAddress((void**)&is, g_iscratch);

    float* XL_OO = sc + OFF_XL_OO;  float* XR_OO = sc + OFF_XR_OO;
    float* XL_OM = sc + OFF_XL_OM;  float* XR_OM = sc + OFF_XR_OM;
    float* XL_MO = sc + OFF_XL_MO;  float* XR_MO = sc + OFF_XR_MO;
    float* RES_OO = sc + OFF_RES_OO; float* RES_MO = sc + OFF_RES_MO;
    float* RES_OM = sc + OFF_RES_OM;
    float* S_OO = sc + OFF_S_OO; float* S_OM = sc + OFF_S_OM; float* S_MO = sc + OFF_S_MO;
    float* OUT_OO = sc + OFF_OUT_OO; float* OUT_MO = sc + OFF_OUT_MO; float* OUT_OM = sc + OFF_OUT_OM;
    float* TMP_OP = sc + OFF_TMP_OP; float* TMP_M = sc + OFF_TMP_M;
    float* BN = sc + OFF_BN;

    int* cnt_oo = is + IOFF_CNT_OO; int* ofs_oo = is + IOFF_OFS_OO;
    int* cur_oo = is + IOFF_CUR_OO; int* el_oo  = is + IOFF_EL_OO;
    int* cnt_om = is + IOFF_CNT_OM; int* ofs_om = is + IOFF_OFS_OM;
    int* cur_om = is + IOFF_CUR_OM; int* el_om  = is + IOFF_EL_OM;
    int* cnt_mo = is + IOFF_CNT_MO; int* ofs_mo = is + IOFF_OFS_MO;
    int* cur_mo = is + IOFF_CUR_MO; int* el_mo  = is + IOFF_EL_MO;

    const int* src_oo = e_oo;
    const int* dst_oo = e_oo + E;

    // ---- dense projections (fp32 tiled GEMM) ----
    auto gemm = [&](const float* A, const float* B, float* C, int M, int N) {
        sgemm<<<dim3(N / 64, (M + 63) / 64), 256>>>(A, B, C, M, N, DIN);
    };
    gemm(x_op, Wl_oo, XL_OO, n_op, HC);
    gemm(x_op, Wr_oo, XR_OO, n_op, HC);
    gemm(x_op, Wl_om, XL_OM, n_op, HC);
    gemm(x_m,  Wr_om, XR_OM, n_m,  HC);
    gemm(x_m,  Wl_mo, XL_MO, n_m,  HC);
    gemm(x_op, Wr_mo, XR_MO, n_op, HC);
    gemm(x_op, Wres_oo, RES_OO, n_op, CC);
    gemm(x_op, Wres_mo, RES_MO, n_op, CC);
    gemm(x_m,  Wres_om, RES_OM, n_m,  CC);

    // ---- zero int scratch + BN accumulators ----
    cudaMemsetAsync(is, 0, TOTAL_I * sizeof(int), 0);
    cudaMemsetAsync(BN, 0, 256 * sizeof(float), 0);

    // ---- CSR build (counting sort by dst) ----
    hist_kernel<<<(Eoo + 255) / 256, 256>>>(dst_oo, Eoo, E, 1, cnt_oo);
    exscan_kernel<<<1, 1024>>>(cnt_oo, ofs_oo, n_op);
    scatter_kernel<<<(Eoo + 255) / 256, 256>>>(dst_oo, Eoo, E, 1, ofs_oo, cur_oo, el_oo);

    hist_kernel<<<(E + 255) / 256, 256>>>(dst_om, E, E, 0, cnt_om);
    exscan_kernel<<<1, 1024>>>(cnt_om, ofs_om, n_m);
    scatter_kernel<<<(E + 255) / 256, 256>>>(dst_om, E, E, 0, ofs_om, cur_om, el_om);

    hist_kernel<<<(E + 255) / 256, 256>>>(dst_mo, E, E, 0, cnt_mo);
    exscan_kernel<<<1, 1024>>>(cnt_mo, ofs_mo, n_op);
    scatter_kernel<<<(E + 255) / 256, 256>>>(dst_mo, E, E, 0, ofs_mo, cur_mo, el_mo);

    // ---- per-edge attention logits ----
    edge_logits<<<(Eoo + 7) / 8, 256>>>(XL_OO, XR_OO, src_oo, dst_oo, Eoo, E, 1, att_oo, S_OO);
    edge_logits<<<(E + 7) / 8, 256>>>(XL_OM, XR_OM, src_om, dst_om, E, E, 0, att_om, S_OM);
    edge_logits<<<(E + 7) / 8, 256>>>(XL_MO, XR_MO, src_mo, dst_mo, E, E, 0, att_mo, S_MO);

    // ---- segment softmax + weighted aggregation (warp per destination) ----
    aggregate<<<(n_op + 7) / 8, 256>>>(XL_OO, S_OO, ofs_oo, el_oo, src_oo, E, 1, n_op, OUT_OO);
    aggregate<<<(n_m + 7) / 8, 256>>>(XL_OM, S_OM, ofs_om, el_om, src_om, E, 0, n_m, OUT_OM);
    aggregate<<<(n_op + 7) / 8, 256>>>(XL_MO, S_MO, ofs_mo, el_mo, src_mo, E, 0, n_op, OUT_MO);

    // ---- combine + BN + ELU ----
    combine_op<<<(n_op * 64 + 255) / 256, 256>>>(OUT_OO, RES_OO, bias_oo,
                                                 OUT_MO, RES_MO, bias_mo,
                                                 TMP_OP, n_op * 64);
    combine_m<<<(n_m * 64 + 255) / 256, 256>>>(OUT_OM, RES_OM, bias_om, TMP_M, n_m * 64);

    bn_reduce<<<184, 256>>>(TMP_OP, n_op, BN);
    bn_reduce<<<184, 256>>>(TMP_M,  n_m,  BN + 128);

    float* out_op = (float*)d_out;
    float* out_m  = (float*)d_out + (long long)n_op * 64;
    bn_apply<<<(n_op * 64 + 255) / 256, 256>>>(TMP_OP, BN,       g_op, b_op, n_op, out_op);
    bn_apply<<<(n_m  * 64 + 255) / 256, 256>>>(TMP_M,  BN + 128, g_m,  b_m,  n_m,  out_m);
}

// round 2
// speedup vs baseline: 1.4393x; 1.4393x over previous
#include <cuda_runtime.h>
#include <math.h>

// ---------------------------------------------------------------------------
// HGATv2: packed fp32 GEMMs (128x128 tiles) + fused online-softmax GAT
// n_op=50000, n_m=10000, E=400000, DIN=128, H=4, C=64
// ---------------------------------------------------------------------------

#define HC 256
#define CC 64
#define DIN 128
#define NEG_SLOPE 0.2f

#define NP_OP 1152   // packed cols: Wl_oo|Wr_oo|Wl_om|Wr_mo|Wres_oo|Wres_mo
#define NP_M  640    // packed cols: Wr_om|Wl_mo|Wres_om|pad64

#define MAX_NOP 50000
#define MAX_NM  10000
#define MAX_E   400000

// ---- float scratch (element offsets) ----
#define OFF_P_OP   0ll                       // 50000*1152 = 57,600,000
#define OFF_P_M    57600000ll                // 10000*640  =  6,400,000
#define OFF_WP_OP  64000000ll                // 128*1152   =    147,456
#define OFF_WP_M   64147456ll                // 128*640    =     81,920
#define OFF_OUT_OO 64229376ll                // 3,200,000
#define OFF_OUT_MO 67429376ll                // 3,200,000
#define OFF_OUT_OM 70629376ll                //   640,000
#define OFF_TMP_OP 71269376ll                // 3,200,000
#define OFF_TMP_M  74469376ll                //   640,000
#define OFF_BN     75109376ll                //       256
#define TOTAL_F    75109632ll

// ---- int scratch ----
#define IOFF_CNT_OO   0ll
#define IOFF_OFS_OO   50000ll
#define IOFF_CUR_OO   100001ll
#define IOFF_EL_OO    150001ll
#define IOFF_CNT_OM   600001ll
#define IOFF_OFS_OM   610001ll
#define IOFF_CUR_OM   620002ll
#define IOFF_EL_OM    630002ll
#define IOFF_CNT_MO   1030002ll
#define IOFF_OFS_MO   1080002ll
#define IOFF_CUR_MO   1130003ll
#define IOFF_EL_MO    1180003ll
#define TOTAL_I       1580003ll

__device__ float g_fscratch[TOTAL_F];
__device__ int   g_iscratch[TOTAL_I];

// ---------------------------------------------------------------------------
// Weight packing
// ---------------------------------------------------------------------------
__global__ void pack_w_op(const float* __restrict__ Wl_oo, const float* __restrict__ Wr_oo,
                          const float* __restrict__ Wl_om, const float* __restrict__ Wr_mo,
                          const float* __restrict__ Wres_oo, const float* __restrict__ Wres_mo,
                          float* __restrict__ P)
{
    int i = blockIdx.x * blockDim.x + threadIdx.x;
    if (i >= 128 * NP_OP) return;
    int k = i / NP_OP, c = i % NP_OP;
    float v;
    if      (c < 256)  v = Wl_oo[k * 256 + c];
    else if (c < 512)  v = Wr_oo[k * 256 + c - 256];
    else if (c < 768)  v = Wl_om[k * 256 + c - 512];
    else if (c < 1024) v = Wr_mo[k * 256 + c - 768];
    else if (c < 1088) v = Wres_oo[k * 64 + c - 1024];
    else               v = Wres_mo[k * 64 + c - 1088];
    P[i] = v;
}

__global__ void pack_w_m(const float* __restrict__ Wr_om, const float* __restrict__ Wl_mo,
                         const float* __restrict__ Wres_om, float* __restrict__ P)
{
    int i = blockIdx.x * blockDim.x + threadIdx.x;
    if (i >= 128 * NP_M) return;
    int k = i / NP_M, c = i % NP_M;
    float v;
    if      (c < 256) v = Wr_om[k * 256 + c];
    else if (c < 512) v = Wl_mo[k * 256 + c - 256];
    else if (c < 576) v = Wres_om[k * 64 + c - 512];
    else              v = 0.f;
    P[i] = v;
}

// ---------------------------------------------------------------------------
// 128x128x16 fp32 GEMM, 8x8 per thread. N must be a multiple of 128, K of 16.
// ---------------------------------------------------------------------------
__global__ void __launch_bounds__(256, 2)
sgemm128(const float* __restrict__ A, const float* __restrict__ B,
         float* __restrict__ C, int M, int N, int K)
{
    __shared__ float As[16][128];
    __shared__ float Bs[16][128];
    const int tid  = threadIdx.x;
    const int brow = blockIdx.y * 128;
    const int bcol = blockIdx.x * 128;
    const int ty = tid >> 4, tx = tid & 15;
    const int ar  = tid >> 1, akq = (tid & 1) * 8;
    const int bkr = tid >> 4, bcq = (tid & 15) * 8;

    float acc[8][8];
    #pragma unroll
    for (int i = 0; i < 8; i++)
        #pragma unroll
        for (int j = 0; j < 8; j++) acc[i][j] = 0.f;

    const bool aval = (brow + ar) < M;
    const float* Abase = A + (size_t)(brow + ar) * K + akq;
    const float* Bbase = B + (size_t)bkr * N + bcol + bcq;

    for (int k0 = 0; k0 < K; k0 += 16) {
        float4 a0 = make_float4(0.f,0.f,0.f,0.f), a1 = a0;
        if (aval) {
            a0 = *(const float4*)(Abase + k0);
            a1 = *(const float4*)(Abase + k0 + 4);
        }
        As[akq+0][ar] = a0.x; As[akq+1][ar] = a0.y;
        As[akq+2][ar] = a0.z; As[akq+3][ar] = a0.w;
        As[akq+4][ar] = a1.x; As[akq+5][ar] = a1.y;
        As[akq+6][ar] = a1.z; As[akq+7][ar] = a1.w;
        const float* bp = Bbase + (size_t)k0 * N;
        *(float4*)&Bs[bkr][bcq]     = *(const float4*)bp;
        *(float4*)&Bs[bkr][bcq + 4] = *(const float4*)(bp + 4);
        __syncthreads();
        #pragma unroll
        for (int kk = 0; kk < 16; kk++) {
            float a[8], b[8];
            *(float4*)(a)     = *(const float4*)&As[kk][ty * 8];
            *(float4*)(a + 4) = *(const float4*)&As[kk][ty * 8 + 4];
            *(float4*)(b)     = *(const float4*)&Bs[kk][tx * 8];
            *(float4*)(b + 4) = *(const float4*)&Bs[kk][tx * 8 + 4];
            #pragma unroll
            for (int i = 0; i < 8; i++)
                #pragma unroll
                for (int j = 0; j < 8; j++) acc[i][j] += a[i] * b[j];
        }
        __syncthreads();
    }
    #pragma unroll
    for (int i = 0; i < 8; i++) {
        int row = brow + ty * 8 + i;
        if (row < M) {
            float4* cp = (float4*)&C[(size_t)row * N + bcol + tx * 8];
            cp[0] = make_float4(acc[i][0], acc[i][1], acc[i][2], acc[i][3]);
            cp[1] = make_float4(acc[i][4], acc[i][5], acc[i][6], acc[i][7]);
        }
    }
}

// ---------------------------------------------------------------------------
// CSR build: histogram -> single-block scan -> scatter
// ---------------------------------------------------------------------------
__global__ void hist_kernel(const int* __restrict__ dst, int ne, int E, int selfloop,
                            int* __restrict__ counts)
{
    int i = blockIdx.x * blockDim.x + threadIdx.x;
    if (i >= ne) return;
    int d = (selfloop && i >= E) ? (i - E) : dst[i];
    atomicAdd(&counts[d], 1);
}

__global__ void exscan_kernel(const int* __restrict__ counts, int* __restrict__ offsets, int n)
{
    __shared__ int sums[1024];
    int t = threadIdx.x;
    int chunk = (n + 1023) / 1024;
    int beg = t * chunk;
    int end = min(beg + chunk, n);
    int s = 0;
    for (int i = beg; i < end; i++) s += counts[i];
    sums[t] = s;
    __syncthreads();
    for (int o = 1; o < 1024; o <<= 1) {
        int v = (t >= o) ? sums[t - o] : 0;
        __syncthreads();
        sums[t] += v;
        __syncthreads();
    }
    int run = sums[t] - s;
    for (int i = beg; i < end; i++) { offsets[i] = run; run += counts[i]; }
    if (t == 1023) offsets[n] = sums[1023];
}

__global__ void scatter_kernel(const int* __restrict__ dst, int ne, int E, int selfloop,
                               const int* __restrict__ offsets, int* __restrict__ cursor,
                               int* __restrict__ elist)
{
    int i = blockIdx.x * blockDim.x + threadIdx.x;
    if (i >= ne) return;
    int d = (selfloop && i >= E) ? (i - E) : dst[i];
    int pos = offsets[d] + atomicAdd(&cursor[d], 1);
    elist[pos] = i;
}

// ---------------------------------------------------------------------------
// Fused GATv2: per-destination warp, online softmax, single XL gather per edge
// ---------------------------------------------------------------------------
__global__ void gat_fused(const float* __restrict__ XL, int ls,
                          const float* __restrict__ XR, int rs,
                          const float* __restrict__ att,
                          const int* __restrict__ offsets,
                          const int* __restrict__ elist,
                          const int* __restrict__ src,
                          int E, int selfloop, int n_dst,
                          float* __restrict__ OUT)
{
    int w    = (blockIdx.x * blockDim.x + threadIdx.x) >> 5;
    int lane = threadIdx.x & 31;
    if (w >= n_dst) return;
    int beg = offsets[w], end = offsets[w + 1];
    const int fb = lane * 2;

    const float4* xrp = (const float4*)(XR + (size_t)w * rs);
    float4 r0 = xrp[fb], r1 = xrp[fb + 1];
    float4 t0 = ((const float4*)att)[fb], t1 = ((const float4*)att)[fb + 1];

    float m = -1e30f, d = 0.f;
    float acc[8];
    #pragma unroll
    for (int k = 0; k < 8; k++) acc[k] = 0.f;

    for (int i = beg; i < end; i++) {
        int e = elist[i];
        int si = (selfloop && e >= E) ? (e - E) : src[e];
        const float4* xlp = (const float4*)(XL + (size_t)si * ls);
        float4 a0 = xlp[fb], a1 = xlp[fb + 1];
        float v, s = 0.f;
        v = a0.x + r0.x; v = v > 0.f ? v : NEG_SLOPE * v; s += v * t0.x;
        v = a0.y + r0.y; v = v > 0.f ? v : NEG_SLOPE * v; s += v * t0.y;
        v = a0.z + r0.z; v = v > 0.f ? v : NEG_SLOPE * v; s += v * t0.z;
        v = a0.w + r0.w; v = v > 0.f ? v : NEG_SLOPE * v; s += v * t0.w;
        v = a1.x + r1.x; v = v > 0.f ? v : NEG_SLOPE * v; s += v * t1.x;
        v = a1.y + r1.y; v = v > 0.f ? v : NEG_SLOPE * v; s += v * t1.y;
        v = a1.z + r1.z; v = v > 0.f ? v : NEG_SLOPE * v; s += v * t1.z;
        v = a1.w + r1.w; v = v > 0.f ? v : NEG_SLOPE * v; s += v * t1.w;
        // per-head reduction over the 8 lanes of this head
        s += __shfl_xor_sync(0xffffffffu, s, 1);
        s += __shfl_xor_sync(0xffffffffu, s, 2);
        s += __shfl_xor_sync(0xffffffffu, s, 4);
        // online softmax update
        float nm = fmaxf(m, s);
        float sc = __expf(m - nm);
        float p  = __expf(s - nm);
        m = nm;
        d = d * sc + p;
        acc[0] = acc[0] * sc + p * a0.x;
        acc[1] = acc[1] * sc + p * a0.y;
        acc[2] = acc[2] * sc + p * a0.z;
        acc[3] = acc[3] * sc + p * a0.w;
        acc[4] = acc[4] * sc + p * a1.x;
        acc[5] = acc[5] * sc + p * a1.y;
        acc[6] = acc[6] * sc + p * a1.z;
        acc[7] = acc[7] * sc + p * a1.w;
    }

    float invd = 1.f / fmaxf(d, 1e-16f);
    #pragma unroll
    for (int k = 0; k < 8; k++) {
        float v = acc[k] * invd;
        v += __shfl_xor_sync(0xffffffffu, v, 8);
        v += __shfl_xor_sync(0xffffffffu, v, 16);
        acc[k] = v * 0.25f;     // mean over 4 heads
    }
    if (lane < 8) {
        float4* op = (float4*)(OUT + (size_t)w * CC);
        op[lane * 2]     = make_float4(acc[0], acc[1], acc[2], acc[3]);
        op[lane * 2 + 1] = make_float4(acc[4], acc[5], acc[6], acc[7]);
    }
}

// ---------------------------------------------------------------------------
// Epilogue
// ---------------------------------------------------------------------------
__global__ void combine_op(const float* __restrict__ A, const float* __restrict__ B,
                           const float* __restrict__ P,   // P_OP: res at cols 1024/1088
                           const float* __restrict__ ba, const float* __restrict__ bb,
                           float* __restrict__ T, int n)
{
    int i = blockIdx.x * blockDim.x + threadIdx.x;
    if (i >= n * 64) return;
    int r = i >> 6, c = i & 63;
    float va = A[i] + P[(size_t)r * NP_OP + 1024 + c] + ba[c];
    float vb = B[i] + P[(size_t)r * NP_OP + 1088 + c] + bb[c];
    T[i] = fmaxf(va, vb);
}

__global__ void combine_m(const float* __restrict__ A, const float* __restrict__ P,
                          const float* __restrict__ ba, float* __restrict__ T, int n)
{
    int i = blockIdx.x * blockDim.x + threadIdx.x;
    if (i >= n * 64) return;
    int r = i >> 6, c = i & 63;
    T[i] = A[i] + P[(size_t)r * NP_M + 512 + c] + ba[c];
}

__global__ void bn_reduce(const float* __restrict__ X, int n, float* __restrict__ acc)
{
    int c  = threadIdx.x & 63;
    int r0 = threadIdx.x >> 6;
    float s = 0.f, q = 0.f;
    for (int r = blockIdx.x * 4 + r0; r < n; r += gridDim.x * 4) {
        float v = X[(size_t)r * 64 + c];
        s += v; q += v * v;
    }
    __shared__ float sh[2][256];
    sh[0][threadIdx.x] = s; sh[1][threadIdx.x] = q;
    __syncthreads();
    if (threadIdx.x < 64) {
        #pragma unroll
        for (int k = 1; k < 4; k++) {
            s += sh[0][threadIdx.x + 64 * k];
            q += sh[1][threadIdx.x + 64 * k];
        }
        atomicAdd(&acc[c], s);
        atomicAdd(&acc[64 + c], q);
    }
}

__global__ void bn_apply(const float* __restrict__ X, const float* __restrict__ acc,
                         const float* __restrict__ gamma, const float* __restrict__ beta,
                         int n, float* __restrict__ out)
{
    int i = blockIdx.x * blockDim.x + threadIdx.x;
    if (i >= n * 64) return;
    int c = i & 63;
    float inv_n = 1.f / (float)n;
    float mu = acc[c] * inv_n;
    float var = acc[64 + c] * inv_n - mu * mu;
    float rstd = rsqrtf(var + 1e-5f);
    float y = (X[i] - mu) * rstd * gamma[c] + beta[c];
    out[i] = y > 0.f ? y : expm1f(y);
}

// ---------------------------------------------------------------------------
// Host launch
// ---------------------------------------------------------------------------
extern "C" void kernel_launch(void* const* d_in, const int* in_sizes, int n_in,
                              void* d_out, int out_size)
{
    const float* x_op   = (const float*)d_in[0];
    const float* x_m    = (const float*)d_in[1];
    const int*   e_oo   = (const int*)  d_in[2];
    const int*   src_om = (const int*)  d_in[3];
    const int*   dst_om = (const int*)  d_in[4];
    const int*   src_mo = (const int*)  d_in[5];
    const int*   dst_mo = (const int*)  d_in[6];
    const float* Wl_oo  = (const float*)d_in[7];
    const float* Wr_oo  = (const float*)d_in[8];
    const float* att_oo = (const float*)d_in[9];
    const float* bias_oo= (const float*)d_in[10];
    const float* Wres_oo= (const float*)d_in[11];
    const float* Wl_om  = (const float*)d_in[12];
    const float* Wr_om  = (const float*)d_in[13];
    const float* att_om = (const float*)d_in[14];
    const float* bias_om= (const float*)d_in[15];
    const float* Wres_om= (const float*)d_in[16];
    const float* Wl_mo  = (const float*)d_in[17];
    const float* Wr_mo  = (const float*)d_in[18];
    const float* att_mo = (const float*)d_in[19];
    const float* bias_mo= (const float*)d_in[20];
    const float* Wres_mo= (const float*)d_in[21];
    const float* g_op   = (const float*)d_in[22];
    const float* b_op   = (const float*)d_in[23];
    const float* g_m    = (const float*)d_in[24];
    const float* b_m    = (const float*)d_in[25];

    const int n_op = in_sizes[0] / DIN;
    const int n_m  = in_sizes[1] / DIN;
    const int E    = in_sizes[3];
    const int Eoo  = E + n_op;

    float* sc; cudaGetSymbolAddress((void**)&sc, g_fscratch);
    int*   is; cudaGetSymbolAddress((void**)&is, g_iscratch);

    float* P_OP  = sc + OFF_P_OP;
    float* P_M   = sc + OFF_P_M;
    float* WP_OP = sc + OFF_WP_OP;
    float* WP_M  = sc + OFF_WP_M;
    float* OUT_OO = sc + OFF_OUT_OO;
    float* OUT_MO = sc + OFF_OUT_MO;
    float* OUT_OM = sc + OFF_OUT_OM;
    float* TMP_OP = sc + OFF_TMP_OP;
    float* TMP_M  = sc + OFF_TMP_M;
    float* BN     = sc + OFF_BN;

    int* cnt_oo = is + IOFF_CNT_OO; int* ofs_oo = is + IOFF_OFS_OO;
    int* cur_oo = is + IOFF_CUR_OO; int* el_oo  = is + IOFF_EL_OO;
    int* cnt_om = is + IOFF_CNT_OM; int* ofs_om = is + IOFF_OFS_OM;
    int* cur_om = is + IOFF_CUR_OM; int* el_om  = is + IOFF_EL_OM;
    int* cnt_mo = is + IOFF_CNT_MO; int* ofs_mo = is + IOFF_OFS_MO;
    int* cur_mo = is + IOFF_CUR_MO; int* el_mo  = is + IOFF_EL_MO;

    const int* src_oo = e_oo;
    const int* dst_oo = e_oo + E;

    // ---- zero int scratch + BN accumulators (in-stream, safe for graph) ----
    cudaMemsetAsync(is, 0, TOTAL_I * sizeof(int), 0);
    cudaMemsetAsync(BN, 0, 256 * sizeof(float), 0);

    // ---- pack weights ----
    pack_w_op<<<(128 * NP_OP + 255) / 256, 256>>>(Wl_oo, Wr_oo, Wl_om, Wr_mo,
                                                  Wres_oo, Wres_mo, WP_OP);
    pack_w_m<<<(128 * NP_M + 255) / 256, 256>>>(Wr_om, Wl_mo, Wres_om, WP_M);

    // ---- CSR build ----
    hist_kernel<<<(Eoo + 255) / 256, 256>>>(dst_oo, Eoo, E, 1, cnt_oo);
    exscan_kernel<<<1, 1024>>>(cnt_oo, ofs_oo, n_op);
    scatter_kernel<<<(Eoo + 255) / 256, 256>>>(dst_oo, Eoo, E, 1, ofs_oo, cur_oo, el_oo);

    hist_kernel<<<(E + 255) / 256, 256>>>(dst_om, E, E, 0, cnt_om);
    exscan_kernel<<<1, 1024>>>(cnt_om, ofs_om, n_m);
    scatter_kernel<<<(E + 255) / 256, 256>>>(dst_om, E, E, 0, ofs_om, cur_om, el_om);

    hist_kernel<<<(E + 255) / 256, 256>>>(dst_mo, E, E, 0, cnt_mo);
    exscan_kernel<<<1, 1024>>>(cnt_mo, ofs_mo, n_op);
    scatter_kernel<<<(E + 255) / 256, 256>>>(dst_mo, E, E, 0, ofs_mo, cur_mo, el_mo);

    // ---- packed projections: one GEMM per node type ----
    sgemm128<<<dim3(NP_OP / 128, (n_op + 127) / 128), 256>>>(x_op, WP_OP, P_OP, n_op, NP_OP, DIN);
    sgemm128<<<dim3(NP_M  / 128, (n_m  + 127) / 128), 256>>>(x_m,  WP_M,  P_M,  n_m,  NP_M,  DIN);

    // ---- fused GAT per edge type ----
    // columns in P_OP: XL_OO=0, XR_OO=256, XL_OM=512, XR_MO=768
    // columns in P_M : XR_OM=0, XL_MO=256
    gat_fused<<<(Eoo ? (n_op + 7) / 8 : 1), 256>>>(P_OP + 0,   NP_OP, P_OP + 256, NP_OP,
                                                   att_oo, ofs_oo, el_oo, src_oo,
                                                   E, 1, n_op, OUT_OO);
    gat_fused<<<(n_m + 7) / 8, 256>>>(P_OP + 512, NP_OP, P_M + 0,    NP_M,
                                      att_om, ofs_om, el_om, src_om,
                                      E, 0, n_m, OUT_OM);
    gat_fused<<<(n_op + 7) / 8, 256>>>(P_M + 256,  NP_M,  P_OP + 768, NP_OP,
                                       att_mo, ofs_mo, el_mo, src_mo,
                                       E, 0, n_op, OUT_MO);

    // ---- combine + BN + ELU ----
    combine_op<<<(n_op * 64 + 255) / 256, 256>>>(OUT_OO, OUT_MO, P_OP, bias_oo, bias_mo,
                                                 TMP_OP, n_op);
    combine_m<<<(n_m * 64 + 255) / 256, 256>>>(OUT_OM, P_M, bias_om, TMP_M, n_m);

    bn_reduce<<<184, 256>>>(TMP_OP, n_op, BN);
    bn_reduce<<<184, 256>>>(TMP_M,  n_m,  BN + 128);

    float* out_op = (float*)d_out;
    float* out_m  = (float*)d_out + (size_t)n_op * 64;
    bn_apply<<<(n_op * 64 + 255) / 256, 256>>>(TMP_OP, BN,       g_op, b_op, n_op, out_op);
    bn_apply<<<(n_m  * 64 + 255) / 256, 256>>>(TMP_M,  BN + 128, g_m,  b_m,  n_m,  out_m);
}